// round 4
// baseline (speedup 1.0000x reference)
#include <cuda_runtime.h>
#include <cstdint>

// ============================================================================
// GCN layer: out = relu(diag(d) A diag(d) X W + b), d = rsqrt(rowsum(A))
// Plan: d = rsqrt(rowsum A); Zt[n,k] = tf32_rn(d_k * (X@W)[k,n]);
//       Y = A @ Zt^T via mma.sync tf32 (K-split=2); out = relu(d_m*Y + b_n).
// Baseline sm_103 ISA only (no tcgen05 — toolchain targets non-'a').
// ============================================================================

#define NROWS 8192
#define FDIM  128
#define ODIM  128

__device__ __align__(128) float g_d[NROWS];
__device__ __align__(128) float g_Zt[ODIM * NROWS];                 // [n][k] K-major
__device__ __align__(128) float g_part[2 * (size_t)NROWS * ODIM];   // K-split partials

// ---------------------------------------------------------------------------
__device__ __forceinline__ uint32_t smem_u32(const void* p) {
    uint32_t a;
    asm("{ .reg .u64 t; cvta.to.shared.u64 t, %1; cvt.u32.u64 %0, t; }"
        : "=r"(a) : "l"(p));
    return a;
}

#define CPA16(dst, src) \
    asm volatile("cp.async.cg.shared.global [%0], [%1], 16;" :: "r"(dst), "l"(src) : "memory")
#define CPA_COMMIT() asm volatile("cp.async.commit_group;" ::: "memory")
#define CPA_WAIT(n)  asm volatile("cp.async.wait_group %0;" :: "n"(n) : "memory")

__device__ __forceinline__ void mma_tf32(float* c, const uint32_t* a, const uint32_t* b) {
    asm volatile(
        "mma.sync.aligned.m16n8k8.row.col.f32.tf32.tf32.f32 "
        "{%0,%1,%2,%3}, {%4,%5,%6,%7}, {%8,%9}, {%0,%1,%2,%3};"
        : "+f"(c[0]), "+f"(c[1]), "+f"(c[2]), "+f"(c[3])
        : "r"(a[0]), "r"(a[1]), "r"(a[2]), "r"(a[3]), "r"(b[0]), "r"(b[1]));
}

// ---------------------------------------------------------------------------
// Kernel 1: d[r] = rsqrt(sum_k A[r,k])
// ---------------------------------------------------------------------------
__global__ __launch_bounds__(256) void rowsum_kernel(const float* __restrict__ A) {
    int row = blockIdx.x;
    const float4* p = reinterpret_cast<const float4*>(A + (size_t)row * NROWS);
    float s = 0.f;
#pragma unroll
    for (int i = 0; i < 8; ++i) {
        float4 v = p[threadIdx.x + i * 256];
        s += (v.x + v.y) + (v.z + v.w);
    }
#pragma unroll
    for (int o = 16; o; o >>= 1) s += __shfl_xor_sync(0xffffffffu, s, o);
    __shared__ float ws[8];
    if ((threadIdx.x & 31) == 0) ws[threadIdx.x >> 5] = s;
    __syncthreads();
    if (threadIdx.x < 8) {
        float t = ws[threadIdx.x];
        t += __shfl_xor_sync(0xffu, t, 4);
        t += __shfl_xor_sync(0xffu, t, 2);
        t += __shfl_xor_sync(0xffu, t, 1);
        if (threadIdx.x == 0) g_d[row] = rsqrtf(t);
    }
}

// ---------------------------------------------------------------------------
// Kernel 2: Zt[n,k] = tf32_rn( d[k] * sum_f X[k,f] W[f,n] )
// ---------------------------------------------------------------------------
__global__ __launch_bounds__(256) void xw_kernel(const float* __restrict__ X,
                                                 const float* __restrict__ W) {
    __shared__ float Ws[128 * 64];
    __shared__ float Xs[16 * 128];
    int tid = threadIdx.x;
    int n0 = blockIdx.y * 64;
    int k0 = blockIdx.x * 16;
    for (int i = tid; i < 128 * 64; i += 256) {
        int f = i >> 6, nl = i & 63;
        Ws[i] = W[f * ODIM + n0 + nl];
    }
    for (int i = tid; i < 16 * 128; i += 256)
        Xs[i] = X[(size_t)(k0 + (i >> 7)) * FDIM + (i & 127)];
    __syncthreads();

    int nl = tid & 63, ks = tid >> 6;
    for (int kk = ks; kk < 16; kk += 4) {
        float acc = 0.f;
#pragma unroll 8
        for (int f = 0; f < 128; ++f) acc += Xs[kk * 128 + f] * Ws[f * 64 + nl];
        int k = k0 + kk;
        float zt = g_d[k] * acc;
        uint32_t u;
        asm("cvt.rna.tf32.f32 %0, %1;" : "=r"(u) : "f"(zt));  // RN round to tf32
        g_Zt[(size_t)(n0 + nl) * NROWS + k] = __uint_as_float(u);
    }
}

// ---------------------------------------------------------------------------
// Kernel 3: partial[ksplit] = A[:, khalf] @ Zt[:, khalf]^T  (mma.sync tf32)
// grid (64, 2); 128 threads (4 warps, 2x2); CTA tile 128x128; k-tile 32.
// 4-stage cp.async pipeline; SW128 XOR swizzle (conflict-free frag loads).
// ---------------------------------------------------------------------------
static constexpr int STG        = 4;
static constexpr int KT         = 32;
static constexpr int KC         = NROWS / 2;      // 4096 per K-split
static constexpr int NKT        = KC / KT;        // 128
static constexpr int STAGE_FLTS = 2 * 128 * KT;   // A + B = 8192 floats = 32KB
static constexpr int DYN_SMEM   = STG * STAGE_FLTS * 4;  // 128KB

__device__ __forceinline__ void ld_tile(uint32_t sbase, int it,
                                        const float* __restrict__ A,
                                        int m0, int kbase, int tid) {
    int k0 = kbase + it * KT;
#pragma unroll
    for (int i = 0; i < 16; ++i) {
        int c   = i * 128 + tid;       // 0..2047 (A: 0..1023, B: 1024..2047)
        int isB = c >> 10;
        int rc  = c & 1023;
        int row = rc >> 3, seg = rc & 7;
        const float* src = isB
            ? (g_Zt + (size_t)row * NROWS + k0 + seg * 4)
            : (A + (size_t)(m0 + row) * NROWS + k0 + seg * 4);
        uint32_t off = (uint32_t)(row * 128 + seg * 16);
        off ^= (off >> 3) & 0x70;      // SW128 swizzle
        CPA16(sbase + (uint32_t)isB * 16384u + off, src);
    }
}

__global__ __launch_bounds__(128, 1) void gemm_kernel(const float* __restrict__ A) {
    extern __shared__ __align__(16) float sm[];
    int tid = threadIdx.x, wid = tid >> 5, lane = tid & 31;
    int m0 = blockIdx.x * 128;
    int kbase = blockIdx.y * KC;
    int mw = (wid >> 1) * 64, nw = (wid & 1) * 64;
    int r = lane >> 2, q = lane & 3;
    uint32_t smb = smem_u32(sm);

    float acc[4][8][4];
#pragma unroll
    for (int i = 0; i < 4; ++i)
#pragma unroll
        for (int j = 0; j < 8; ++j)
#pragma unroll
            for (int v = 0; v < 4; ++v) acc[i][j][v] = 0.f;

    // prologue: stages 0..STG-2
#pragma unroll
    for (int s = 0; s < STG - 1; ++s) {
        ld_tile(smb + s * STAGE_FLTS * 4, s, A, m0, kbase, tid);
        CPA_COMMIT();
    }

    for (int it = 0; it < NKT; ++it) {
        CPA_WAIT(STG - 2);
        __syncthreads();
        // issue next load (overwrites slot of stage it-1, consumed & synced)
        if (it + STG - 1 < NKT)
            ld_tile(smb + ((it + STG - 1) % STG) * STAGE_FLTS * 4,
                    it + STG - 1, A, m0, kbase, tid);
        CPA_COMMIT();

        const float* sa = sm + (it % STG) * STAGE_FLTS;
        const float* sb = sa + 128 * KT;
#pragma unroll
        for (int ks = 0; ks < 4; ++ks) {
            int c0 = q + ks * 8;
            uint32_t a[4][4], b[8][2];
#pragma unroll
            for (int i = 0; i < 4; ++i) {
                int r0 = mw + i * 16 + r;
                int r1 = r0 + 8;
                int x0 = 4 * (r0 & 7), x1 = 4 * (r1 & 7);
                a[i][0] = __float_as_uint(sa[r0 * 32 + (c0 ^ x0)]);
                a[i][1] = __float_as_uint(sa[r1 * 32 + (c0 ^ x1)]);
                a[i][2] = __float_as_uint(sa[r0 * 32 + ((c0 + 4) ^ x0)]);
                a[i][3] = __float_as_uint(sa[r1 * 32 + ((c0 + 4) ^ x1)]);
            }
#pragma unroll
            for (int j = 0; j < 8; ++j) {
                int n0 = nw + j * 8 + r;
                int xn = 4 * (n0 & 7);
                b[j][0] = __float_as_uint(sb[n0 * 32 + (c0 ^ xn)]);
                b[j][1] = __float_as_uint(sb[n0 * 32 + ((c0 + 4) ^ xn)]);
            }
#pragma unroll
            for (int i = 0; i < 4; ++i)
#pragma unroll
                for (int j = 0; j < 8; ++j)
                    mma_tf32(acc[i][j], a[i], b[j]);
        }
    }
    CPA_WAIT(0);

    // write partials (no relu yet)
    float* P = g_part + (size_t)blockIdx.y * NROWS * ODIM;
#pragma unroll
    for (int i = 0; i < 4; ++i) {
        int row0 = m0 + mw + i * 16 + r;
#pragma unroll
        for (int j = 0; j < 8; ++j) {
            int col = nw + j * 8 + 2 * q;
            *reinterpret_cast<float2*>(&P[(size_t)row0 * ODIM + col]) =
                make_float2(acc[i][j][0], acc[i][j][1]);
            *reinterpret_cast<float2*>(&P[(size_t)(row0 + 8) * ODIM + col]) =
                make_float2(acc[i][j][2], acc[i][j][3]);
        }
    }
}

// ---------------------------------------------------------------------------
// Kernel 4: out = relu(d_m * (p0 + p1) + b_n)
// ---------------------------------------------------------------------------
__global__ __launch_bounds__(256) void combine_kernel(const float* __restrict__ bias,
                                                      float* __restrict__ out) {
    int i = blockIdx.x * 256 + threadIdx.x;            // float4 index, 262144 total
    const float4* P0 = reinterpret_cast<const float4*>(g_part);
    const float4* P1 = P0 + (size_t)NROWS * ODIM / 4;
    int m = i >> 5;
    int c = (i & 31) * 4;
    float4 p0 = P0[i], p1 = P1[i];
    float4 bb = *reinterpret_cast<const float4*>(bias + c);
    float dv = g_d[m];
    float4 o;
    o.x = fmaxf(fmaf(dv, p0.x + p1.x, bb.x), 0.f);
    o.y = fmaxf(fmaf(dv, p0.y + p1.y, bb.y), 0.f);
    o.z = fmaxf(fmaf(dv, p0.z + p1.z, bb.z), 0.f);
    o.w = fmaxf(fmaf(dv, p0.w + p1.w, bb.w), 0.f);
    reinterpret_cast<float4*>(out)[i] = o;
}

// ---------------------------------------------------------------------------
extern "C" void kernel_launch(void* const* d_in, const int* in_sizes, int n_in,
                              void* d_out, int out_size) {
    const float* A = (const float*)d_in[0];
    const float* X = (const float*)d_in[1];
    const float* W = (const float*)d_in[2];
    const float* b = (const float*)d_in[3];
    float* out = (float*)d_out;
    (void)in_sizes; (void)n_in; (void)out_size;

    rowsum_kernel<<<NROWS, 256>>>(A);
    dim3 g2(NROWS / 16, 2);
    xw_kernel<<<g2, 256>>>(X, W);
    cudaFuncSetAttribute(gemm_kernel,
                         cudaFuncAttributeMaxDynamicSharedMemorySize, DYN_SMEM);
    dim3 g3(NROWS / 128, 2);
    gemm_kernel<<<g3, 128, DYN_SMEM>>>(A);
    combine_kernel<<<NROWS * ODIM / 4 / 256, 256>>>(b, out);
}